// round 1
// baseline (speedup 1.0000x reference)
#include <cuda_runtime.h>
#include <stdint.h>

#define NPG  39
#define FDIM 3280
#define BGR  4096
#define MAXE (NPG * 9)   // 312 regular + 39 self loops

// Feature-matrix layout offsets (concat order from reference):
// res(39) | res1(312) | res2(2496) | res3(351) | out0(1) | out1(8) | out2(64) | out3(9)
#define OFF_RES1 39
#define OFF_RES2 351
#define OFF_RES3 2847
#define OFF_OUT0 3198
#define OFF_OUT1 3199
#define OFF_OUT2 3207
#define OFF_OUT3 3271

// Scratch (device globals: allocation-free per harness rules)
__device__ float g_F[(size_t)BGR * FDIM];   // 53.7 MB
__device__ float g_G[(size_t)BGR * 5000];   // 81.9 MB
__device__ float g_H[(size_t)BGR * 1024];   // 16.8 MB
__device__ int   g_is64;

// ---------------------------------------------------------------------------
// edge_index dtype sniff: src = repeat(arange(N), 8).
// int32 data: word[8] = src[8] = 1.  int64 data: word[8] = low(src[4]) = 0.
__global__ void k_sniff(const int* __restrict__ ei) {
    if (threadIdx.x == 0) g_is64 = (ei[8] == 0) ? 1 : 0;
}

// ---------------------------------------------------------------------------
// res (x reshape) + out0 (per-graph max of x)
__global__ void k_res0(const float* __restrict__ x, float* __restrict__ F) {
    int g = blockIdx.x;
    __shared__ float sx[NPG];
    int t = threadIdx.x;
    if (t < NPG) {
        float v = x[g * NPG + t];
        sx[t] = v;
        F[(size_t)g * FDIM + t] = v;
    }
    __syncthreads();
    if (t == 0) {
        float mv = sx[0];
        for (int i = 1; i < NPG; i++) mv = fmaxf(mv, sx[i]);
        F[(size_t)g * FDIM + OFF_OUT0] = mv;
    }
}

// monotone float<->uint encode for atomicMax on signed floats
__device__ __forceinline__ unsigned fenc(float f) {
    unsigned u = __float_as_uint(f);
    return (u & 0x80000000u) ? ~u : (u | 0x80000000u);
}
__device__ __forceinline__ float fdec(unsigned u) {
    return (u & 0x80000000u) ? __uint_as_float(u & 0x7FFFFFFFu)
                             : __uint_as_float(~u);
}

// ---------------------------------------------------------------------------
// One GAT layer, one CTA per graph. Entire graph (h, scores, softmax,
// aggregation) lives in shared memory. Writes relu'd output to the reshape
// block of F and the per-feature segment max block.
template <int FIN, int FOUT>
__global__ __launch_bounds__(256) void k_gat(
    const float* __restrict__ X, int gstride,
    const void* __restrict__ edges, int E, int EPG,
    const float* __restrict__ W, const float* __restrict__ as_,
    const float* __restrict__ ad_, const float* __restrict__ bias,
    float* __restrict__ F, int res_off, int max_off)
{
    __shared__ float sx[NPG * FIN];
    __shared__ float sW[FIN * FOUT];
    __shared__ float sas[FOUT], sad[FOUT], sb[FOUT];
    __shared__ float sh[NPG * FOUT];
    __shared__ float sacc[NPG * FOUT];
    __shared__ float ss[NPG], sd[NPG], sden[NPG];
    __shared__ unsigned sm[NPG];
    __shared__ float ew[MAXE];
    __shared__ short els[MAXE], eld[MAXE];

    int g = blockIdx.x;
    int t = threadIdx.x;
    const float* xg = X + (size_t)g * gstride;
    int nE = EPG + NPG;

    for (int i = t; i < NPG * FIN; i += 256) sx[i] = xg[i];
    for (int i = t; i < FIN * FOUT; i += 256) sW[i] = W[i];
    if (t < FOUT) { sas[t] = as_[t]; sad[t] = ad_[t]; sb[t] = bias[t]; }
    __syncthreads();

    // h = x @ W (linear, no bias, no relu before attention)
    for (int idx = t; idx < NPG * FOUT; idx += 256) {
        int i = idx / FOUT, f = idx - i * FOUT;
        float a = 0.f;
        #pragma unroll
        for (int k = 0; k < FIN; k++) a += sx[i * FIN + k] * sW[k * FOUT + f];
        sh[idx] = a;
        sacc[idx] = 0.f;
    }
    __syncthreads();

    // per-node attention projections + init
    for (int i = t; i < NPG; i += 256) {
        float a = 0.f, b = 0.f;
        #pragma unroll
        for (int f = 0; f < FOUT; f++) {
            a += sh[i * FOUT + f] * sas[f];
            b += sh[i * FOUT + f] * sad[f];
        }
        ss[i] = a; sd[i] = b; sden[i] = 0.f; sm[i] = 0u;
    }
    __syncthreads();

    bool is64 = (g_is64 != 0);
    long long node0 = (long long)g * NPG;

    // pass 1: leaky-relu scores + segment max (shared atomics)
    for (int e = t; e < nE; e += 256) {
        int ls, ld;
        if (e < EPG) {
            long long ge = (long long)g * EPG + e;
            long long sv, dv;
            if (is64) {
                const long long* p = (const long long*)edges;
                sv = p[ge]; dv = p[ge + E];
            } else {
                const int* p = (const int*)edges;
                sv = p[ge]; dv = p[ge + E];
            }
            ls = (int)(sv - node0);
            ld = (int)(dv - node0);
        } else {
            ls = ld = e - EPG;   // self loop
        }
        els[e] = (short)ls; eld[e] = (short)ld;
        float ev = ss[ls] + sd[ld];
        ev = ev > 0.f ? ev : 0.2f * ev;
        ew[e] = ev;
        atomicMax(&sm[ld], fenc(ev));
    }
    __syncthreads();

    // pass 2: exp(e - m), denom
    for (int e = t; e < nE; e += 256) {
        float w = __expf(ew[e] - fdec(sm[eld[e]]));
        ew[e] = w;
        atomicAdd(&sden[eld[e]], w);
    }
    __syncthreads();

    // pass 3: weighted aggregation into acc
    for (int idx = t; idx < nE * FOUT; idx += 256) {
        int e = idx / FOUT, f = idx - e * FOUT;
        atomicAdd(&sacc[(int)eld[e] * FOUT + f], ew[e] * sh[(int)els[e] * FOUT + f]);
    }
    __syncthreads();

    // epilogue: divide, bias, relu, write reshape block; then feature max
    float* Fg = F + (size_t)g * FDIM;
    for (int idx = t; idx < NPG * FOUT; idx += 256) {
        int i = idx / FOUT, f = idx - i * FOUT;
        float v = sacc[idx] / (sden[i] + 1e-16f) + sb[f];
        v = fmaxf(v, 0.f);
        Fg[res_off + idx] = v;
        sh[idx] = v;   // reuse for max
    }
    __syncthreads();
    for (int f = t; f < FOUT; f += 256) {
        float mv = sh[f];
        for (int i = 1; i < NPG; i++) mv = fmaxf(mv, sh[i * FOUT + f]);
        Fg[max_off + f] = mv;
    }
}

// ---------------------------------------------------------------------------
// fp32 tiled GEMM: C[M,N] = act(A[M,K] @ B[K,N] + bias).
// 128x128 block tile, 8x8 per-thread tile, K-step 8, float4 loads.
// Assumes M % 128 == 0 and K % 8 == 0 (true: M=4096, K in {3280, 5000}).
template <bool RELU>
__global__ __launch_bounds__(256) void k_sgemm(
    const float* __restrict__ A, const float* __restrict__ B,
    const float* __restrict__ bias, float* __restrict__ C,
    int M, int N, int K)
{
    __shared__ float As[8][128];
    __shared__ float Bs[8][128];

    int tid = threadIdx.x;
    int bn = blockIdx.x * 128;
    int bm = blockIdx.y * 128;
    int tx = tid & 15, ty = tid >> 4;

    float acc[8][8];
    #pragma unroll
    for (int i = 0; i < 8; i++)
        #pragma unroll
        for (int j = 0; j < 8; j++) acc[i][j] = 0.f;

    int arow = tid >> 1, ak = (tid & 1) * 4;
    int bk = tid >> 5, bcol = (tid & 31) * 4;
    const float* Ap = A + (size_t)(bm + arow) * K + ak;
    const float* Bp = B + (size_t)bk * N + bn + bcol;
    int gcol = bn + bcol;
    bool bfull = (gcol + 3 < N);

    for (int k0 = 0; k0 < K; k0 += 8) {
        float4 av = *(const float4*)(Ap + k0);
        As[ak + 0][arow] = av.x;
        As[ak + 1][arow] = av.y;
        As[ak + 2][arow] = av.z;
        As[ak + 3][arow] = av.w;

        float4 bv;
        if (bfull) {
            bv = *(const float4*)(Bp + (size_t)k0 * N);
        } else {
            bv.x = (gcol + 0 < N) ? Bp[(size_t)k0 * N + 0] : 0.f;
            bv.y = (gcol + 1 < N) ? Bp[(size_t)k0 * N + 1] : 0.f;
            bv.z = (gcol + 2 < N) ? Bp[(size_t)k0 * N + 2] : 0.f;
            bv.w = (gcol + 3 < N) ? Bp[(size_t)k0 * N + 3] : 0.f;
        }
        *(float4*)&Bs[bk][bcol] = bv;
        __syncthreads();

        #pragma unroll
        for (int kk = 0; kk < 8; kk++) {
            float ar[8], br[8];
            *(float4*)(ar)     = *(const float4*)&As[kk][ty * 8];
            *(float4*)(ar + 4) = *(const float4*)&As[kk][ty * 8 + 4];
            *(float4*)(br)     = *(const float4*)&Bs[kk][tx * 8];
            *(float4*)(br + 4) = *(const float4*)&Bs[kk][tx * 8 + 4];
            #pragma unroll
            for (int i = 0; i < 8; i++)
                #pragma unroll
                for (int j = 0; j < 8; j++)
                    acc[i][j] += ar[i] * br[j];
        }
        __syncthreads();
    }

    int row0 = bm + ty * 8, col0 = bn + tx * 8;
    #pragma unroll
    for (int i = 0; i < 8; i++) {
        float* Crow = C + (size_t)(row0 + i) * N;
        #pragma unroll
        for (int j = 0; j < 8; j++) {
            int c = col0 + j;
            if (c < N) {
                float v = acc[i][j] + bias[c];
                if (RELU) v = fmaxf(v, 0.f);
                Crow[c] = v;
            }
        }
    }
}

// ---------------------------------------------------------------------------
// skinny final layer: out[M,9] = H[M,1024] @ W[1024,9] + b
__global__ void k_lin3(const float* __restrict__ H, const float* __restrict__ W,
                       const float* __restrict__ b, float* __restrict__ out, int M)
{
    int idx = blockIdx.x * blockDim.x + threadIdx.x;
    if (idx >= M * 9) return;
    int row = idx / 9, c = idx - row * 9;
    const float* h = H + (size_t)row * 1024;
    float acc = 0.f;
    #pragma unroll 8
    for (int k = 0; k < 1024; k++) acc += h[k] * W[k * 9 + c];
    out[idx] = acc + b[c];
}

// ---------------------------------------------------------------------------
extern "C" void kernel_launch(void* const* d_in, const int* in_sizes, int n_in,
                              void* d_out, int out_size)
{
    const float* x   = (const float*)d_in[0];
    const void*  ei  = d_in[1];
    // d_in[2] = batch_vec (unused; graph id = node / 39)
    const float* W1  = (const float*)d_in[3];
    const float* a1s = (const float*)d_in[4];
    const float* a1d = (const float*)d_in[5];
    const float* b1  = (const float*)d_in[6];
    const float* W2  = (const float*)d_in[7];
    const float* a2s = (const float*)d_in[8];
    const float* a2d = (const float*)d_in[9];
    const float* b2  = (const float*)d_in[10];
    const float* W3  = (const float*)d_in[11];
    const float* a3s = (const float*)d_in[12];
    const float* a3d = (const float*)d_in[13];
    const float* b3  = (const float*)d_in[14];
    const float* lW1 = (const float*)d_in[15];
    const float* lb1 = (const float*)d_in[16];
    const float* lW2 = (const float*)d_in[17];
    const float* lb2 = (const float*)d_in[18];
    const float* lW3 = (const float*)d_in[19];
    const float* lb3 = (const float*)d_in[20];

    int N   = in_sizes[0];      // 159744
    int B   = N / NPG;          // 4096
    int E   = in_sizes[1] / 2;  // 1277952
    int EPG = E / B;            // 312

    float *F, *G, *H;
    cudaGetSymbolAddress((void**)&F, g_F);
    cudaGetSymbolAddress((void**)&G, g_G);
    cudaGetSymbolAddress((void**)&H, g_H);

    k_sniff<<<1, 32>>>((const int*)ei);
    k_res0<<<B, 64>>>(x, F);

    k_gat<1, 8><<<B, 256>>>(x, NPG, ei, E, EPG, W1, a1s, a1d, b1,
                            F, OFF_RES1, OFF_OUT1);
    k_gat<8, 64><<<B, 256>>>(F + OFF_RES1, FDIM, ei, E, EPG, W2, a2s, a2d, b2,
                             F, OFF_RES2, OFF_OUT2);
    k_gat<64, 9><<<B, 256>>>(F + OFF_RES2, FDIM, ei, E, EPG, W3, a3s, a3d, b3,
                             F, OFF_RES3, OFF_OUT3);

    // MLP
    {
        dim3 grid((5000 + 127) / 128, B / 128);
        k_sgemm<true><<<grid, 256>>>(F, lW1, lb1, G, B, 5000, FDIM);
    }
    {
        dim3 grid(1024 / 128, B / 128);
        k_sgemm<true><<<grid, 256>>>(G, lW2, lb2, H, B, 1024, 5000);
    }
    k_lin3<<<(B * 9 + 255) / 256, 256>>>(H, lW3, lb3, (float*)d_out, B);
}

// round 4
// speedup vs baseline: 2.0255x; 2.0255x over previous
#include <cuda_runtime.h>
#include <cuda_bf16.h>
#include <stdint.h>

#define NPG  39
#define FDIM 3280
#define BGR  4096
#define MAXE (NPG * 9)

#define OFF_RES1 39
#define OFF_RES2 351
#define OFF_RES3 2847
#define OFF_OUT0 3198
#define OFF_OUT1 3199
#define OFF_OUT2 3207
#define OFF_OUT3 3271

// GEMM1: K=3280 -> Kp=3328, K'=9984 ; N=5000 padded to 5120 rows
// GEMM2: K=5000 -> Kp=5056, K'=15168; N=1024
#define K1P 3328
#define K1T (3*K1P)
#define K2P 5056
#define K2T (3*K2P)
#define N1PAD 5120

// ---- scratch (device globals; zero-initialized -> padding stays 0) ----
__device__ float g_F[(size_t)BGR * FDIM];
__device__ float g_G[(size_t)BGR * 5000];
__device__ float g_H[(size_t)BGR * 1024];
__device__ __nv_bfloat16 g_A1[(size_t)BGR * K1T];
__device__ __nv_bfloat16 g_B1[(size_t)N1PAD * K1T];
__device__ __nv_bfloat16 g_A2[(size_t)BGR * K2T];
__device__ __nv_bfloat16 g_B2[(size_t)1024 * K2T];
__device__ int g_is64;

__device__ __forceinline__ uint32_t smem_u32(const void* p) {
    uint32_t a;
    asm("{ .reg .u64 t; cvta.to.shared.u64 t, %1; cvt.u32.u64 %0, t; }"
        : "=r"(a) : "l"(p));
    return a;
}

// ===================== misc small kernels =====================
__global__ void k_sniff(const int* __restrict__ ei) {
    if (threadIdx.x == 0) g_is64 = (ei[8] == 0) ? 1 : 0;
}

__global__ void k_res0(const float* __restrict__ x, float* __restrict__ F) {
    int g = blockIdx.x;
    __shared__ float sx[NPG];
    int t = threadIdx.x;
    if (t < NPG) {
        float v = x[g * NPG + t];
        sx[t] = v;
        F[(size_t)g * FDIM + t] = v;
    }
    __syncthreads();
    if (t == 0) {
        float mv = sx[0];
        for (int i = 1; i < NPG; i++) mv = fmaxf(mv, sx[i]);
        F[(size_t)g * FDIM + OFF_OUT0] = mv;
    }
}

__device__ __forceinline__ unsigned fenc(float f) {
    unsigned u = __float_as_uint(f);
    return (u & 0x80000000u) ? ~u : (u | 0x80000000u);
}
__device__ __forceinline__ float fdec(unsigned u) {
    return (u & 0x80000000u) ? __uint_as_float(u & 0x7FFFFFFFu)
                             : __uint_as_float(~u);
}

// ===================== GAT layer (passed R1) =====================
template <int FIN, int FOUT>
__global__ __launch_bounds__(256) void k_gat(
    const float* __restrict__ X, int gstride,
    const void* __restrict__ edges, int E, int EPG,
    const float* __restrict__ W, const float* __restrict__ as_,
    const float* __restrict__ ad_, const float* __restrict__ bias,
    float* __restrict__ F, int res_off, int max_off)
{
    __shared__ float sx[NPG * FIN];
    __shared__ float sW[FIN * FOUT];
    __shared__ float sas[FOUT], sad[FOUT], sb[FOUT];
    __shared__ float sh[NPG * FOUT];
    __shared__ float sacc[NPG * FOUT];
    __shared__ float ss[NPG], sd[NPG], sden[NPG];
    __shared__ unsigned sm[NPG];
    __shared__ float ew[MAXE];
    __shared__ short els[MAXE], eld[MAXE];

    int g = blockIdx.x;
    int t = threadIdx.x;
    const float* xg = X + (size_t)g * gstride;
    int nE = EPG + NPG;

    for (int i = t; i < NPG * FIN; i += 256) sx[i] = xg[i];
    for (int i = t; i < FIN * FOUT; i += 256) sW[i] = W[i];
    if (t < FOUT) { sas[t] = as_[t]; sad[t] = ad_[t]; sb[t] = bias[t]; }
    __syncthreads();

    for (int idx = t; idx < NPG * FOUT; idx += 256) {
        int i = idx / FOUT, f = idx - i * FOUT;
        float a = 0.f;
        #pragma unroll
        for (int k = 0; k < FIN; k++) a += sx[i * FIN + k] * sW[k * FOUT + f];
        sh[idx] = a;
        sacc[idx] = 0.f;
    }
    __syncthreads();

    for (int i = t; i < NPG; i += 256) {
        float a = 0.f, b = 0.f;
        #pragma unroll
        for (int f = 0; f < FOUT; f++) {
            a += sh[i * FOUT + f] * sas[f];
            b += sh[i * FOUT + f] * sad[f];
        }
        ss[i] = a; sd[i] = b; sden[i] = 0.f; sm[i] = 0u;
    }
    __syncthreads();

    bool is64 = (g_is64 != 0);
    long long node0 = (long long)g * NPG;

    for (int e = t; e < nE; e += 256) {
        int ls, ld;
        if (e < EPG) {
            long long ge = (long long)g * EPG + e;
            long long sv, dv;
            if (is64) {
                const long long* p = (const long long*)edges;
                sv = p[ge]; dv = p[ge + E];
            } else {
                const int* p = (const int*)edges;
                sv = p[ge]; dv = p[ge + E];
            }
            ls = (int)(sv - node0);
            ld = (int)(dv - node0);
        } else {
            ls = ld = e - EPG;
        }
        els[e] = (short)ls; eld[e] = (short)ld;
        float ev = ss[ls] + sd[ld];
        ev = ev > 0.f ? ev : 0.2f * ev;
        ew[e] = ev;
        atomicMax(&sm[ld], fenc(ev));
    }
    __syncthreads();

    for (int e = t; e < nE; e += 256) {
        float w = __expf(ew[e] - fdec(sm[eld[e]]));
        ew[e] = w;
        atomicAdd(&sden[eld[e]], w);
    }
    __syncthreads();

    for (int idx = t; idx < nE * FOUT; idx += 256) {
        int e = idx / FOUT, f = idx - e * FOUT;
        atomicAdd(&sacc[(int)eld[e] * FOUT + f], ew[e] * sh[(int)els[e] * FOUT + f]);
    }
    __syncthreads();

    float* Fg = F + (size_t)g * FDIM;
    for (int idx = t; idx < NPG * FOUT; idx += 256) {
        int i = idx / FOUT, f = idx - i * FOUT;
        float v = sacc[idx] / (sden[i] + 1e-16f) + sb[f];
        v = fmaxf(v, 0.f);
        Fg[res_off + idx] = v;
        sh[idx] = v;
    }
    __syncthreads();
    for (int f = t; f < FOUT; f += 256) {
        float mv = sh[f];
        for (int i = 1; i < NPG; i++) mv = fmaxf(mv, sh[i * FOUT + f]);
        Fg[max_off + f] = mv;
    }
}

// ===================== split/prep kernels =====================
// A' = [hi | hi | lo] along K (row-major, row stride 3*Kp)
__global__ void k_splitA(const float* __restrict__ src, __nv_bfloat16* __restrict__ dst,
                         int M, int K, int Kp)
{
    long long n = (long long)M * K;
    long long i = (long long)blockIdx.x * blockDim.x + threadIdx.x;
    long long stride = (long long)gridDim.x * blockDim.x;
    for (; i < n; i += stride) {
        int m = (int)(i / K), k = (int)(i - (long long)m * K);
        float v = src[i];
        __nv_bfloat16 hi = __float2bfloat16(v);
        __nv_bfloat16 lo = __float2bfloat16(v - __bfloat162float(hi));
        __nv_bfloat16* row = dst + (size_t)m * (3 * Kp);
        row[k] = hi;
        row[Kp + k] = hi;
        row[2 * Kp + k] = lo;
    }
}

// B' = transpose(W[K,N]) -> [N rows, 3*Kp cols] = [hi | lo | hi]
__global__ void k_splitB(const float* __restrict__ W, __nv_bfloat16* __restrict__ Bt,
                         int K, int N, int Kp)
{
    __shared__ float tile[32][33];
    int kb = blockIdx.y * 32, nb = blockIdx.x * 32;
    int tx = threadIdx.x, ty = threadIdx.y;
    for (int r = ty; r < 32; r += 8) {
        int k = kb + r, n = nb + tx;
        tile[r][tx] = (k < K && n < N) ? W[(size_t)k * N + n] : 0.f;
    }
    __syncthreads();
    for (int r = ty; r < 32; r += 8) {
        int n = nb + r, k = kb + tx;
        if (n < N && k < K) {
            float v = tile[tx][r];
            __nv_bfloat16 hi = __float2bfloat16(v);
            __nv_bfloat16 lo = __float2bfloat16(v - __bfloat162float(hi));
            __nv_bfloat16* row = Bt + (size_t)n * (3 * Kp);
            row[k] = hi;
            row[Kp + k] = lo;
            row[2 * Kp + k] = hi;
        }
    }
}

// ===================== mma.sync GEMM =====================
// C[M,Nreal] = relu(A'[M,Kt] @ B'[Npad,Kt]^T + bias)  (both K-major)
// CTA 128x256, 8 warps (2x4), warp tile 64x64, BK=32, 3-stage cp.async.
#define ROWB 80            // smem row stride bytes (64 data + 16 pad)
#define A_STG (128 * ROWB) // 10240
#define B_STG (256 * ROWB) // 20480
#define STG   (A_STG + B_STG)
#define GEMM_SMEM (3 * STG) // 92160

__device__ __forceinline__ void ldm4(uint32_t* r, uint32_t addr) {
    asm volatile("ldmatrix.sync.aligned.m8n8.x4.shared.b16 {%0,%1,%2,%3}, [%4];"
        : "=r"(r[0]), "=r"(r[1]), "=r"(r[2]), "=r"(r[3]) : "r"(addr));
}
__device__ __forceinline__ void mma16816(float* c, const uint32_t* a,
                                         uint32_t b0, uint32_t b1) {
    asm volatile("mma.sync.aligned.m16n8k16.row.col.f32.bf16.bf16.f32 "
        "{%0,%1,%2,%3}, {%4,%5,%6,%7}, {%8,%9}, {%0,%1,%2,%3};"
        : "+f"(c[0]), "+f"(c[1]), "+f"(c[2]), "+f"(c[3])
        : "r"(a[0]), "r"(a[1]), "r"(a[2]), "r"(a[3]), "r"(b0), "r"(b1));
}

template <bool GUARD>
__global__ __launch_bounds__(256, 1) void k_mma(
    const __nv_bfloat16* __restrict__ A, const __nv_bfloat16* __restrict__ B,
    const float* __restrict__ bias, float* __restrict__ C,
    int Kt, int steps, int Nreal)
{
    extern __shared__ char smem[];
    uint32_t sb = smem_u32(smem);
    int tid = threadIdx.x;
    int lane = tid & 31, wid = tid >> 5;
    int wm = wid & 1, wn = wid >> 1;
    int bm = blockIdx.y * 128, bn = blockIdx.x * 256;

    const char* Abase = (const char*)A + (size_t)bm * Kt * 2;
    const char* Bbase = (const char*)B + (size_t)bn * Kt * 2;
    size_t gsA = (size_t)Kt * 2;

    auto load_stage = [&](int s, int slot) {
        size_t kb = (size_t)s * 64;
        uint32_t base = sb + slot * STG;
        #pragma unroll
        for (int i = 0; i < 2; i++) {              // A: 512 chunks
            int c = tid + i * 256;
            int row = c >> 2, kc = c & 3;
            uint32_t dst = base + row * ROWB + kc * 16;
            const char* src = Abase + (size_t)row * gsA + kb + kc * 16;
            asm volatile("cp.async.cg.shared.global [%0], [%1], 16;"
                         :: "r"(dst), "l"(src));
        }
        #pragma unroll
        for (int i = 0; i < 4; i++) {              // B: 1024 chunks
            int c = tid + i * 256;
            int row = c >> 2, kc = c & 3;
            uint32_t dst = base + A_STG + row * ROWB + kc * 16;
            const char* src = Bbase + (size_t)row * gsA + kb + kc * 16;
            asm volatile("cp.async.cg.shared.global [%0], [%1], 16;"
                         :: "r"(dst), "l"(src));
        }
    };

    float acc[4][8][4];
    #pragma unroll
    for (int i = 0; i < 4; i++)
        #pragma unroll
        for (int j = 0; j < 8; j++)
            #pragma unroll
            for (int q = 0; q < 4; q++) acc[i][j][q] = 0.f;

    load_stage(0, 0);
    asm volatile("cp.async.commit_group;" ::: "memory");
    load_stage(1, 1);
    asm volatile("cp.async.commit_group;" ::: "memory");

    // per-thread ldmatrix address components
    int lr = lane & 15;            // row within 16
    int lc = (lane >> 4) * 16;     // byte offset for k half

    for (int j = 0; j < steps; j++) {
        asm volatile("cp.async.wait_group 1;" ::: "memory");
        __syncthreads();

        if (j + 2 < steps) load_stage(j + 2, (j + 2) % 3);
        asm volatile("cp.async.commit_group;" ::: "memory");

        uint32_t sA = sb + (j % 3) * STG;
        uint32_t sB = sA + A_STG;
        uint32_t aA = sA + (wm * 64 + lr) * ROWB + lc;
        uint32_t aB = sB + (wn * 64 + lr) * ROWB + lc;

        #pragma unroll
        for (int ks = 0; ks < 2; ks++) {
            uint32_t a[4][4], b[4][4];
            #pragma unroll
            for (int mi = 0; mi < 4; mi++)
                ldm4(a[mi], aA + mi * 16 * ROWB + ks * 32);
            #pragma unroll
            for (int ng = 0; ng < 4; ng++)
                ldm4(b[ng], aB + ng * 16 * ROWB + ks * 32);
            #pragma unroll
            for (int mi = 0; mi < 4; mi++)
                #pragma unroll
                for (int ng = 0; ng < 4; ng++) {
                    mma16816(acc[mi][2 * ng],     a[mi], b[ng][0], b[ng][2]);
                    mma16816(acc[mi][2 * ng + 1], a[mi], b[ng][1], b[ng][3]);
                }
        }
        __syncthreads();
    }

    // epilogue: bias + relu, direct stores
    int r0base = bm + wm * 64 + (lane >> 2);
    int c0base = bn + wn * 64 + (lane & 3) * 2;
    #pragma unroll
    for (int mi = 0; mi < 4; mi++) {
        #pragma unroll
        for (int ni = 0; ni < 8; ni++) {
            int col = c0base + ni * 8;
            if (GUARD && col >= Nreal) continue;
            float bv0 = __ldg(&bias[col]);
            float bv1 = (!GUARD || col + 1 < Nreal) ? __ldg(&bias[col + 1]) : 0.f;
            int r0 = r0base + mi * 16;
            int r1 = r0 + 8;
            float v0 = fmaxf(acc[mi][ni][0] + bv0, 0.f);
            float v1 = fmaxf(acc[mi][ni][1] + bv1, 0.f);
            float v2 = fmaxf(acc[mi][ni][2] + bv0, 0.f);
            float v3 = fmaxf(acc[mi][ni][3] + bv1, 0.f);
            if (!GUARD || col + 1 < Nreal) {
                *(float2*)(C + (size_t)r0 * Nreal + col) = make_float2(v0, v1);
                *(float2*)(C + (size_t)r1 * Nreal + col) = make_float2(v2, v3);
            } else {
                C[(size_t)r0 * Nreal + col] = v0;
                C[(size_t)r1 * Nreal + col] = v2;
            }
        }
    }
}

// ===================== final skinny layer =====================
__global__ void k_lin3(const float* __restrict__ H, const float* __restrict__ W,
                       const float* __restrict__ b, float* __restrict__ out, int M)
{
    int idx = blockIdx.x * blockDim.x + threadIdx.x;
    if (idx >= M * 9) return;
    int row = idx / 9, c = idx - row * 9;
    const float* h = H + (size_t)row * 1024;
    float acc = 0.f;
    #pragma unroll 8
    for (int k = 0; k < 1024; k++) acc += h[k] * W[k * 9 + c];
    out[idx] = acc + b[c];
}

// ===================== launch =====================
extern "C" void kernel_launch(void* const* d_in, const int* in_sizes, int n_in,
                              void* d_out, int out_size)
{
    const float* x   = (const float*)d_in[0];
    const void*  ei  = d_in[1];
    const float* W1  = (const float*)d_in[3];
    const float* a1s = (const float*)d_in[4];
    const float* a1d = (const float*)d_in[5];
    const float* b1  = (const float*)d_in[6];
    const float* W2  = (const float*)d_in[7];
    const float* a2s = (const float*)d_in[8];
    const float* a2d = (const float*)d_in[9];
    const float* b2  = (const float*)d_in[10];
    const float* W3  = (const float*)d_in[11];
    const float* a3s = (const float*)d_in[12];
    const float* a3d = (const float*)d_in[13];
    const float* b3  = (const float*)d_in[14];
    const float* lW1 = (const float*)d_in[15];
    const float* lb1 = (const float*)d_in[16];
    const float* lW2 = (const float*)d_in[17];
    const float* lb2 = (const float*)d_in[18];
    const float* lW3 = (const float*)d_in[19];
    const float* lb3 = (const float*)d_in[20];

    int N   = in_sizes[0];
    int B   = N / NPG;
    int E   = in_sizes[1] / 2;
    int EPG = E / B;

    float *F, *G, *H;
    __nv_bfloat16 *A1, *B1, *A2, *B2;
    cudaGetSymbolAddress((void**)&F, g_F);
    cudaGetSymbolAddress((void**)&G, g_G);
    cudaGetSymbolAddress((void**)&H, g_H);
    cudaGetSymbolAddress((void**)&A1, g_A1);
    cudaGetSymbolAddress((void**)&B1, g_B1);
    cudaGetSymbolAddress((void**)&A2, g_A2);
    cudaGetSymbolAddress((void**)&B2, g_B2);

    cudaFuncSetAttribute(k_mma<true>,
        cudaFuncAttributeMaxDynamicSharedMemorySize, GEMM_SMEM);
    cudaFuncSetAttribute(k_mma<false>,
        cudaFuncAttributeMaxDynamicSharedMemorySize, GEMM_SMEM);

    k_sniff<<<1, 32>>>((const int*)ei);
    k_res0<<<B, 64>>>(x, F);

    k_gat<1, 8><<<B, 256>>>(x, NPG, ei, E, EPG, W1, a1s, a1d, b1,
                            F, OFF_RES1, OFF_OUT1);
    k_gat<8, 64><<<B, 256>>>(F + OFF_RES1, FDIM, ei, E, EPG, W2, a2s, a2d, b2,
                             F, OFF_RES2, OFF_OUT2);
    k_gat<64, 9><<<B, 256>>>(F + OFF_RES2, FDIM, ei, E, EPG, W3, a3s, a3d, b3,
                             F, OFF_RES3, OFF_OUT3);

    {
        dim3 blk(32, 8);
        dim3 g1((5000 + 31) / 32, (3280 + 31) / 32);
        k_splitB<<<g1, blk>>>(lW1, B1, 3280, 5000, K1P);
        dim3 g2((1024 + 31) / 32, (5000 + 31) / 32);
        k_splitB<<<g2, blk>>>(lW2, B2, 5000, 1024, K2P);
    }

    k_splitA<<<4096, 256>>>(F, A1, B, FDIM, K1P);
    {
        dim3 grid(N1PAD / 256, BGR / 128);   // 20 x 32
        k_mma<true><<<grid, 256, GEMM_SMEM>>>(A1, B1, lb1, G,
                                              K1T, K1T / 32, 5000);
    }

    k_splitA<<<4096, 256>>>(G, A2, B, 5000, K2P);
    {
        dim3 grid(1024 / 256, BGR / 128);    // 4 x 32
        k_mma<false><<<grid, 256, GEMM_SMEM>>>(A2, B2, lb2, H,
                                               K2T, K2T / 32, 1024);
    }

    k_lin3<<<(B * 9 + 255) / 256, 256>>>(H, lW3, lb3, (float*)d_out, B);
}

// round 5
// speedup vs baseline: 2.4660x; 1.2175x over previous
#include <cuda_runtime.h>
#include <cuda_bf16.h>
#include <stdint.h>

#define NPG  39
#define FDIM 3280
#define BGR  4096
#define MAXE (NPG * 9)

#define OFF_RES1 39
#define OFF_RES2 351
#define OFF_RES3 2847
#define OFF_OUT0 3198
#define OFF_OUT1 3199
#define OFF_OUT2 3207
#define OFF_OUT3 3271

#define K1P 3328
#define K1T (3*K1P)      // 9984
#define K2P 5056
#define K2T (3*K2P)      // 15168
#define N1PAD 5120

__device__ float g_F[(size_t)BGR * FDIM];
__device__ float g_G[(size_t)BGR * 5000];
__device__ float g_H[(size_t)BGR * 1024];
__device__ __nv_bfloat16 g_A1[(size_t)BGR * K1T];
__device__ __nv_bfloat16 g_B1[(size_t)N1PAD * K1T];
__device__ __nv_bfloat16 g_A2[(size_t)BGR * K2T];
__device__ __nv_bfloat16 g_B2[(size_t)1024 * K2T];
__device__ int g_is64;

__device__ __forceinline__ uint32_t smem_u32(const void* p) {
    uint32_t a;
    asm("{ .reg .u64 t; cvta.to.shared.u64 t, %1; cvt.u32.u64 %0, t; }"
        : "=r"(a) : "l"(p));
    return a;
}

// ===================== misc small kernels =====================
__global__ void k_sniff(const int* __restrict__ ei) {
    if (threadIdx.x == 0) g_is64 = (ei[8] == 0) ? 1 : 0;
}

__global__ void k_res0(const float* __restrict__ x, float* __restrict__ F) {
    int g = blockIdx.x;
    __shared__ float sx[NPG];
    int t = threadIdx.x;
    if (t < NPG) {
        float v = x[g * NPG + t];
        sx[t] = v;
        F[(size_t)g * FDIM + t] = v;
    }
    __syncthreads();
    if (t == 0) {
        float mv = sx[0];
        for (int i = 1; i < NPG; i++) mv = fmaxf(mv, sx[i]);
        F[(size_t)g * FDIM + OFF_OUT0] = mv;
    }
}

__device__ __forceinline__ unsigned fenc(float f) {
    unsigned u = __float_as_uint(f);
    return (u & 0x80000000u) ? ~u : (u | 0x80000000u);
}
__device__ __forceinline__ float fdec(unsigned u) {
    return (u & 0x80000000u) ? __uint_as_float(u & 0x7FFFFFFFu)
                             : __uint_as_float(~u);
}

// ===================== GAT layer: counting-sort by dst, no agg atomics ====
template <int FIN, int FOUT>
__global__ __launch_bounds__(256) void k_gat(
    const float* __restrict__ X, int gstride,
    const void* __restrict__ edges, int E, int EPG,
    const float* __restrict__ W, const float* __restrict__ as_,
    const float* __restrict__ ad_, const float* __restrict__ bias,
    float* __restrict__ F, int res_off, int max_off)
{
    __shared__ float sx[NPG * FIN];
    __shared__ float sW[FIN * FOUT];
    __shared__ float sas[FOUT], sad[FOUT], sb[FOUT];
    __shared__ float sh[NPG * FOUT];
    __shared__ float sout[NPG * FOUT];
    __shared__ float ss[NPG], sd[NPG], sden[NPG];
    __shared__ unsigned sm[NPG];
    __shared__ float ew[MAXE];
    __shared__ short els[MAXE], eld[MAXE];
    __shared__ short sse[MAXE];
    __shared__ float sew[MAXE];
    __shared__ int cnt[NPG + 1], off[NPG];

    int g = blockIdx.x;
    int t = threadIdx.x;
    const float* xg = X + (size_t)g * gstride;
    int nE = EPG + NPG;

    for (int i = t; i < NPG * FIN; i += 256) sx[i] = xg[i];
    for (int i = t; i < FIN * FOUT; i += 256) sW[i] = W[i];
    if (t < FOUT) { sas[t] = as_[t]; sad[t] = ad_[t]; sb[t] = bias[t]; }
    if (t < NPG + 1) cnt[t] = 0;
    __syncthreads();

    // h = x @ W
    for (int idx = t; idx < NPG * FOUT; idx += 256) {
        int i = idx / FOUT, f = idx - i * FOUT;
        float a = 0.f;
        #pragma unroll
        for (int k = 0; k < FIN; k++) a += sx[i * FIN + k] * sW[k * FOUT + f];
        sh[idx] = a;
    }
    __syncthreads();

    for (int i = t; i < NPG; i += 256) {
        float a = 0.f, b = 0.f;
        #pragma unroll
        for (int f = 0; f < FOUT; f++) {
            a += sh[i * FOUT + f] * sas[f];
            b += sh[i * FOUT + f] * sad[f];
        }
        ss[i] = a; sd[i] = b; sm[i] = 0u;
    }
    __syncthreads();

    bool is64 = (g_is64 != 0);
    long long node0 = (long long)g * NPG;

    // pass 1: scores + seg max + histogram
    for (int e = t; e < nE; e += 256) {
        int ls, ld;
        if (e < EPG) {
            long long ge = (long long)g * EPG + e;
            long long sv, dv;
            if (is64) {
                const long long* p = (const long long*)edges;
                sv = p[ge]; dv = p[ge + E];
            } else {
                const int* p = (const int*)edges;
                sv = p[ge]; dv = p[ge + E];
            }
            ls = (int)(sv - node0);
            ld = (int)(dv - node0);
        } else {
            ls = ld = e - EPG;
        }
        els[e] = (short)ls; eld[e] = (short)ld;
        float ev = ss[ls] + sd[ld];
        ev = ev > 0.f ? ev : 0.2f * ev;
        ew[e] = ev;
        atomicMax(&sm[ld], fenc(ev));
        atomicAdd(&cnt[ld], 1);
    }
    __syncthreads();

    if (t == 0) {
        int s = 0;
        for (int i = 0; i < NPG; i++) {
            int c = cnt[i];
            cnt[i] = s; off[i] = s;
            s += c;
        }
        cnt[NPG] = s;
    }
    __syncthreads();

    // scatter (sorted by dst) with exp applied
    for (int e = t; e < nE; e += 256) {
        int ld = eld[e];
        int pos = atomicAdd(&off[ld], 1);
        sew[pos] = __expf(ew[e] - fdec(sm[ld]));
        sse[pos] = els[e];
    }
    __syncthreads();

    // denom per dst (no atomics)
    for (int i = t; i < NPG; i += 256) {
        float s = 0.f;
        for (int e = cnt[i]; e < cnt[i + 1]; e++) s += sew[e];
        sden[i] = s;
    }
    __syncthreads();

    // aggregation: per (node, feature) gather
    float* Fg = F + (size_t)g * FDIM;
    for (int idx = t; idx < NPG * FOUT; idx += 256) {
        int i = idx / FOUT, f = idx - i * FOUT;
        float a = 0.f;
        int e0 = cnt[i], e1 = cnt[i + 1];
        for (int e = e0; e < e1; e++)
            a += sew[e] * sh[(int)sse[e] * FOUT + f];
        float v = a / (sden[i] + 1e-16f) + sb[f];
        v = fmaxf(v, 0.f);
        Fg[res_off + idx] = v;
        sout[idx] = v;
    }
    __syncthreads();
    for (int f = t; f < FOUT; f += 256) {
        float mv = sout[f];
        for (int i = 1; i < NPG; i++) mv = fmaxf(mv, sout[i * FOUT + f]);
        Fg[max_off + f] = mv;
    }
}

// ===================== split/prep kernels =====================
__global__ void k_splitA(const float* __restrict__ src, __nv_bfloat16* __restrict__ dst,
                         int M, int K, int Kp)
{
    long long n = (long long)M * K;
    long long i = (long long)blockIdx.x * blockDim.x + threadIdx.x;
    long long stride = (long long)gridDim.x * blockDim.x;
    for (; i < n; i += stride) {
        int m = (int)(i / K), k = (int)(i - (long long)m * K);
        float v = src[i];
        __nv_bfloat16 hi = __float2bfloat16(v);
        __nv_bfloat16 lo = __float2bfloat16(v - __bfloat162float(hi));
        __nv_bfloat16* row = dst + (size_t)m * (3 * Kp);
        row[k] = hi;
        row[Kp + k] = hi;
        row[2 * Kp + k] = lo;
    }
}

__global__ void k_splitB(const float* __restrict__ W, __nv_bfloat16* __restrict__ Bt,
                         int K, int N, int Kp)
{
    __shared__ float tile[32][33];
    int kb = blockIdx.y * 32, nb = blockIdx.x * 32;
    int tx = threadIdx.x, ty = threadIdx.y;
    for (int r = ty; r < 32; r += 8) {
        int k = kb + r, n = nb + tx;
        tile[r][tx] = (k < K && n < N) ? W[(size_t)k * N + n] : 0.f;
    }
    __syncthreads();
    for (int r = ty; r < 32; r += 8) {
        int n = nb + r, k = kb + tx;
        if (n < N && k < K) {
            float v = tile[tx][r];
            __nv_bfloat16 hi = __float2bfloat16(v);
            __nv_bfloat16 lo = __float2bfloat16(v - __bfloat162float(hi));
            __nv_bfloat16* row = Bt + (size_t)n * (3 * Kp);
            row[k] = hi;
            row[Kp + k] = lo;
            row[2 * Kp + k] = hi;
        }
    }
}

// ===================== mma.sync GEMM =====================
// CTA 128x128, 4 warps (2x2), warp tile 64x64, BK=64, 3 stages, 2 CTAs/SM.
#define ROWB 144           // 128B data + 16B pad
#define A_STG (128 * ROWB) // 18432
#define B_STG (128 * ROWB) // 18432
#define STG   (A_STG + B_STG)
#define GEMM_SMEM (3 * STG) // 110592

__device__ __forceinline__ void ldm4(uint32_t* r, uint32_t addr) {
    asm volatile("ldmatrix.sync.aligned.m8n8.x4.shared.b16 {%0,%1,%2,%3}, [%4];"
        : "=r"(r[0]), "=r"(r[1]), "=r"(r[2]), "=r"(r[3]) : "r"(addr));
}
__device__ __forceinline__ void mma16816(float* c, const uint32_t* a,
                                         uint32_t b0, uint32_t b1) {
    asm volatile("mma.sync.aligned.m16n8k16.row.col.f32.bf16.bf16.f32 "
        "{%0,%1,%2,%3}, {%4,%5,%6,%7}, {%8,%9}, {%0,%1,%2,%3};"
        : "+f"(c[0]), "+f"(c[1]), "+f"(c[2]), "+f"(c[3])
        : "r"(a[0]), "r"(a[1]), "r"(a[2]), "r"(a[3]), "r"(b0), "r"(b1));
}

template <bool GUARD>
__global__ __launch_bounds__(128, 2) void k_mma(
    const __nv_bfloat16* __restrict__ A, const __nv_bfloat16* __restrict__ B,
    const float* __restrict__ bias, float* __restrict__ C,
    int Kt, int steps, int Nreal)
{
    extern __shared__ char smem[];
    uint32_t sb = smem_u32(smem);
    int tid = threadIdx.x;
    int lane = tid & 31, wid = tid >> 5;
    int wm = wid & 1, wn = wid >> 1;     // 2x2 warp grid
    int bm = blockIdx.y * 128, bn = blockIdx.x * 128;

    const char* Abase = (const char*)A + (size_t)bm * Kt * 2;
    const char* Bbase = (const char*)B + (size_t)bn * Kt * 2;
    size_t gsA = (size_t)Kt * 2;

    auto load_stage = [&](int s, int slot) {
        size_t kb = (size_t)s * 128;       // 64 bf16 = 128 bytes
        uint32_t base = sb + slot * STG;
        #pragma unroll
        for (int i = 0; i < 8; i++) {      // A: 1024 16B-chunks / 128 thr
            int c = tid + i * 128;
            int row = c >> 3, kc = c & 7;
            uint32_t dst = base + row * ROWB + kc * 16;
            const char* src = Abase + (size_t)row * gsA + kb + kc * 16;
            asm volatile("cp.async.cg.shared.global [%0], [%1], 16;"
                         :: "r"(dst), "l"(src));
        }
        #pragma unroll
        for (int i = 0; i < 8; i++) {      // B
            int c = tid + i * 128;
            int row = c >> 3, kc = c & 7;
            uint32_t dst = base + A_STG + row * ROWB + kc * 16;
            const char* src = Bbase + (size_t)row * gsA + kb + kc * 16;
            asm volatile("cp.async.cg.shared.global [%0], [%1], 16;"
                         :: "r"(dst), "l"(src));
        }
    };

    float acc[4][8][4];
    #pragma unroll
    for (int i = 0; i < 4; i++)
        #pragma unroll
        for (int j = 0; j < 8; j++)
            #pragma unroll
            for (int q = 0; q < 4; q++) acc[i][j][q] = 0.f;

    load_stage(0, 0);
    asm volatile("cp.async.commit_group;" ::: "memory");
    load_stage(1, 1);
    asm volatile("cp.async.commit_group;" ::: "memory");

    int lr = lane & 15;
    int lc = (lane >> 4) * 16;

    for (int j = 0; j < steps; j++) {
        asm volatile("cp.async.wait_group 1;" ::: "memory");
        __syncthreads();

        if (j + 2 < steps) load_stage(j + 2, (j + 2) % 3);
        asm volatile("cp.async.commit_group;" ::: "memory");

        uint32_t sA = sb + (j % 3) * STG;
        uint32_t sB = sA + A_STG;
        uint32_t aA = sA + (wm * 64 + lr) * ROWB + lc;
        uint32_t aB = sB + (wn * 64 + lr) * ROWB + lc;

        #pragma unroll
        for (int ks = 0; ks < 4; ks++) {
            uint32_t a[4][4], b[4][4];
            #pragma unroll
            for (int mi = 0; mi < 4; mi++)
                ldm4(a[mi], aA + mi * 16 * ROWB + ks * 32);
            #pragma unroll
            for (int ng = 0; ng < 4; ng++)
                ldm4(b[ng], aB + ng * 16 * ROWB + ks * 32);
            #pragma unroll
            for (int mi = 0; mi < 4; mi++)
                #pragma unroll
                for (int ng = 0; ng < 4; ng++) {
                    mma16816(acc[mi][2 * ng],     a[mi], b[ng][0], b[ng][2]);
                    mma16816(acc[mi][2 * ng + 1], a[mi], b[ng][1], b[ng][3]);
                }
        }
        __syncthreads();
    }

    int r0base = bm + wm * 64 + (lane >> 2);
    int c0base = bn + wn * 64 + (lane & 3) * 2;
    #pragma unroll
    for (int mi = 0; mi < 4; mi++) {
        #pragma unroll
        for (int ni = 0; ni < 8; ni++) {
            int col = c0base + ni * 8;
            if (GUARD && col >= Nreal) continue;
            float bv0 = __ldg(&bias[col]);
            float bv1 = (!GUARD || col + 1 < Nreal) ? __ldg(&bias[col + 1]) : 0.f;
            int r0 = r0base + mi * 16;
            int r1 = r0 + 8;
            float v0 = fmaxf(acc[mi][ni][0] + bv0, 0.f);
            float v1 = fmaxf(acc[mi][ni][1] + bv1, 0.f);
            float v2 = fmaxf(acc[mi][ni][2] + bv0, 0.f);
            float v3 = fmaxf(acc[mi][ni][3] + bv1, 0.f);
            if (!GUARD || col + 1 < Nreal) {
                *(float2*)(C + (size_t)r0 * Nreal + col) = make_float2(v0, v1);
                *(float2*)(C + (size_t)r1 * Nreal + col) = make_float2(v2, v3);
            } else {
                C[(size_t)r0 * Nreal + col] = v0;
                C[(size_t)r1 * Nreal + col] = v2;
            }
        }
    }
}

// ===================== final skinny layer =====================
__global__ void k_lin3(const float* __restrict__ H, const float* __restrict__ W,
                       const float* __restrict__ b, float* __restrict__ out, int M)
{
    int idx = blockIdx.x * blockDim.x + threadIdx.x;
    if (idx >= M * 9) return;
    int row = idx / 9, c = idx - row * 9;
    const float* h = H + (size_t)row * 1024;
    float acc = 0.f;
    #pragma unroll 8
    for (int k = 0; k < 1024; k++) acc += h[k] * W[k * 9 + c];
    out[idx] = acc + b[c];
}

// ===================== launch =====================
extern "C" void kernel_launch(void* const* d_in, const int* in_sizes, int n_in,
                              void* d_out, int out_size)
{
    const float* x   = (const float*)d_in[0];
    const void*  ei  = d_in[1];
    const float* W1  = (const float*)d_in[3];
    const float* a1s = (const float*)d_in[4];
    const float* a1d = (const float*)d_in[5];
    const float* b1  = (const float*)d_in[6];
    const float* W2  = (const float*)d_in[7];
    const float* a2s = (const float*)d_in[8];
    const float* a2d = (const float*)d_in[9];
    const float* b2  = (const float*)d_in[10];
    const float* W3  = (const float*)d_in[11];
    const float* a3s = (const float*)d_in[12];
    const float* a3d = (const float*)d_in[13];
    const float* b3  = (const float*)d_in[14];
    const float* lW1 = (const float*)d_in[15];
    const float* lb1 = (const float*)d_in[16];
    const float* lW2 = (const float*)d_in[17];
    const float* lb2 = (const float*)d_in[18];
    const float* lW3 = (const float*)d_in[19];
    const float* lb3 = (const float*)d_in[20];

    int N   = in_sizes[0];
    int B   = N / NPG;
    int E   = in_sizes[1] / 2;
    int EPG = E / B;

    float *F, *G, *H;
    __nv_bfloat16 *A1, *B1, *A2, *B2;
    cudaGetSymbolAddress((void**)&F, g_F);
    cudaGetSymbolAddress((void**)&G, g_G);
    cudaGetSymbolAddress((void**)&H, g_H);
    cudaGetSymbolAddress((void**)&A1, g_A1);
    cudaGetSymbolAddress((void**)&B1, g_B1);
    cudaGetSymbolAddress((void**)&A2, g_A2);
    cudaGetSymbolAddress((void**)&B2, g_B2);

    cudaFuncSetAttribute(k_mma<true>,
        cudaFuncAttributeMaxDynamicSharedMemorySize, GEMM_SMEM);
    cudaFuncSetAttribute(k_mma<false>,
        cudaFuncAttributeMaxDynamicSharedMemorySize, GEMM_SMEM);

    k_sniff<<<1, 32>>>((const int*)ei);
    k_res0<<<B, 64>>>(x, F);

    k_gat<1, 8><<<B, 256>>>(x, NPG, ei, E, EPG, W1, a1s, a1d, b1,
                            F, OFF_RES1, OFF_OUT1);
    k_gat<8, 64><<<B, 256>>>(F + OFF_RES1, FDIM, ei, E, EPG, W2, a2s, a2d, b2,
                             F, OFF_RES2, OFF_OUT2);
    k_gat<64, 9><<<B, 256>>>(F + OFF_RES2, FDIM, ei, E, EPG, W3, a3s, a3d, b3,
                             F, OFF_RES3, OFF_OUT3);

    {
        dim3 blk(32, 8);
        dim3 g1((5000 + 31) / 32, (3280 + 31) / 32);
        k_splitB<<<g1, blk>>>(lW1, B1, 3280, 5000, K1P);
        dim3 g2((1024 + 31) / 32, (5000 + 31) / 32);
        k_splitB<<<g2, blk>>>(lW2, B2, 5000, 1024, K2P);
    }

    k_splitA<<<4096, 256>>>(F, A1, B, FDIM, K1P);
    {
        dim3 grid(N1PAD / 128, BGR / 128);   // 40 x 32
        k_mma<true><<<grid, 128, GEMM_SMEM>>>(A1, B1, lb1, G,
                                              K1T, K1T / 64, 5000);
    }

    k_splitA<<<4096, 256>>>(G, A2, B, 5000, K2P);
    {
        dim3 grid(1024 / 128, BGR / 128);    // 8 x 32
        k_mma<false><<<grid, 128, GEMM_SMEM>>>(A2, B2, lb2, H,
                                               K2T, K2T / 64, 1024);
    }

    k_lin3<<<(B * 9 + 255) / 256, 256>>>(H, lW3, lb3, (float*)d_out, B);
}

// round 6
// speedup vs baseline: 2.5103x; 1.0180x over previous
#include <cuda_runtime.h>
#include <cuda_bf16.h>
#include <stdint.h>

#define NPG  39
#define FDIM 3280
#define BGR  4096
#define MAXE (NPG * 9)

#define OFF_RES1 39
#define OFF_RES2 351
#define OFF_RES3 2847
#define OFF_OUT0 3198
#define OFF_OUT1 3199
#define OFF_OUT2 3207
#define OFF_OUT3 3271

#define K1P 3328
#define K1T (3*K1P)      // 9984
#define K2P 5056
#define K2T (3*K2P)      // 15168
#define N1PAD 5120

__device__ float g_F[(size_t)BGR * FDIM];
__device__ float g_H[(size_t)BGR * 1024];
__device__ __nv_bfloat16 g_A1[(size_t)BGR * K1T];
__device__ __nv_bfloat16 g_B1[(size_t)N1PAD * K1T];
__device__ __nv_bfloat16 g_A2[(size_t)BGR * K2T];
__device__ __nv_bfloat16 g_B2[(size_t)1024 * K2T];
__device__ int g_is64;

__device__ __forceinline__ uint32_t smem_u32(const void* p) {
    uint32_t a;
    asm("{ .reg .u64 t; cvta.to.shared.u64 t, %1; cvt.u32.u64 %0, t; }"
        : "=r"(a) : "l"(p));
    return a;
}

// ===================== misc small kernels =====================
__global__ void k_sniff(const int* __restrict__ ei) {
    if (threadIdx.x == 0) g_is64 = (ei[8] == 0) ? 1 : 0;
}

__global__ void k_res0(const float* __restrict__ x, float* __restrict__ F) {
    int g = blockIdx.x;
    __shared__ float sx[NPG];
    int t = threadIdx.x;
    if (t < NPG) {
        float v = x[g * NPG + t];
        sx[t] = v;
        F[(size_t)g * FDIM + t] = v;
    }
    __syncthreads();
    if (t == 0) {
        float mv = sx[0];
        for (int i = 1; i < NPG; i++) mv = fmaxf(mv, sx[i]);
        F[(size_t)g * FDIM + OFF_OUT0] = mv;
    }
}

__device__ __forceinline__ unsigned fenc(float f) {
    unsigned u = __float_as_uint(f);
    return (u & 0x80000000u) ? ~u : (u | 0x80000000u);
}
__device__ __forceinline__ float fdec(unsigned u) {
    return (u & 0x80000000u) ? __uint_as_float(u & 0x7FFFFFFFu)
                             : __uint_as_float(~u);
}

// ===================== GAT layer (counting-sort, R5) =====================
template <int FIN, int FOUT>
__global__ __launch_bounds__(256) void k_gat(
    const float* __restrict__ X, int gstride,
    const void* __restrict__ edges, int E, int EPG,
    const float* __restrict__ W, const float* __restrict__ as_,
    const float* __restrict__ ad_, const float* __restrict__ bias,
    float* __restrict__ F, int res_off, int max_off)
{
    __shared__ float sx[NPG * FIN];
    __shared__ float sW[FIN * FOUT];
    __shared__ float sas[FOUT], sad[FOUT], sb[FOUT];
    __shared__ float sh[NPG * FOUT];
    __shared__ float sout[NPG * FOUT];
    __shared__ float ss[NPG], sd[NPG], sden[NPG];
    __shared__ unsigned sm[NPG];
    __shared__ float ew[MAXE];
    __shared__ short els[MAXE], eld[MAXE];
    __shared__ short sse[MAXE];
    __shared__ float sew[MAXE];
    __shared__ int cnt[NPG + 1], off[NPG];

    int g = blockIdx.x;
    int t = threadIdx.x;
    const float* xg = X + (size_t)g * gstride;
    int nE = EPG + NPG;

    for (int i = t; i < NPG * FIN; i += 256) sx[i] = xg[i];
    for (int i = t; i < FIN * FOUT; i += 256) sW[i] = W[i];
    if (t < FOUT) { sas[t] = as_[t]; sad[t] = ad_[t]; sb[t] = bias[t]; }
    if (t < NPG + 1) cnt[t] = 0;
    __syncthreads();

    for (int idx = t; idx < NPG * FOUT; idx += 256) {
        int i = idx / FOUT, f = idx - i * FOUT;
        float a = 0.f;
        #pragma unroll
        for (int k = 0; k < FIN; k++) a += sx[i * FIN + k] * sW[k * FOUT + f];
        sh[idx] = a;
    }
    __syncthreads();

    for (int i = t; i < NPG; i += 256) {
        float a = 0.f, b = 0.f;
        #pragma unroll
        for (int f = 0; f < FOUT; f++) {
            a += sh[i * FOUT + f] * sas[f];
            b += sh[i * FOUT + f] * sad[f];
        }
        ss[i] = a; sd[i] = b; sm[i] = 0u;
    }
    __syncthreads();

    bool is64 = (g_is64 != 0);
    long long node0 = (long long)g * NPG;

    for (int e = t; e < nE; e += 256) {
        int ls, ld;
        if (e < EPG) {
            long long ge = (long long)g * EPG + e;
            long long sv, dv;
            if (is64) {
                const long long* p = (const long long*)edges;
                sv = p[ge]; dv = p[ge + E];
            } else {
                const int* p = (const int*)edges;
                sv = p[ge]; dv = p[ge + E];
            }
            ls = (int)(sv - node0);
            ld = (int)(dv - node0);
        } else {
            ls = ld = e - EPG;
        }
        els[e] = (short)ls; eld[e] = (short)ld;
        float ev = ss[ls] + sd[ld];
        ev = ev > 0.f ? ev : 0.2f * ev;
        ew[e] = ev;
        atomicMax(&sm[ld], fenc(ev));
        atomicAdd(&cnt[ld], 1);
    }
    __syncthreads();

    if (t == 0) {
        int s = 0;
        for (int i = 0; i < NPG; i++) {
            int c = cnt[i];
            cnt[i] = s; off[i] = s;
            s += c;
        }
        cnt[NPG] = s;
    }
    __syncthreads();

    for (int e = t; e < nE; e += 256) {
        int ld = eld[e];
        int pos = atomicAdd(&off[ld], 1);
        sew[pos] = __expf(ew[e] - fdec(sm[ld]));
        sse[pos] = els[e];
    }
    __syncthreads();

    for (int i = t; i < NPG; i += 256) {
        float s = 0.f;
        for (int e = cnt[i]; e < cnt[i + 1]; e++) s += sew[e];
        sden[i] = s;
    }
    __syncthreads();

    float* Fg = F + (size_t)g * FDIM;
    for (int idx = t; idx < NPG * FOUT; idx += 256) {
        int i = idx / FOUT, f = idx - i * FOUT;
        float a = 0.f;
        int e0 = cnt[i], e1 = cnt[i + 1];
        for (int e = e0; e < e1; e++)
            a += sew[e] * sh[(int)sse[e] * FOUT + f];
        float v = a / (sden[i] + 1e-16f) + sb[f];
        v = fmaxf(v, 0.f);
        Fg[res_off + idx] = v;
        sout[idx] = v;
    }
    __syncthreads();
    for (int f = t; f < FOUT; f += 256) {
        float mv = sout[f];
        for (int i = 1; i < NPG; i++) mv = fmaxf(mv, sout[i * FOUT + f]);
        Fg[max_off + f] = mv;
    }
}

// ===================== split/prep kernels =====================
__global__ void k_splitA(const float* __restrict__ src, __nv_bfloat16* __restrict__ dst,
                         int M, int K, int Kp)
{
    long long n = (long long)M * K;
    long long i = (long long)blockIdx.x * blockDim.x + threadIdx.x;
    long long stride = (long long)gridDim.x * blockDim.x;
    for (; i < n; i += stride) {
        int m = (int)(i / K), k = (int)(i - (long long)m * K);
        float v = src[i];
        __nv_bfloat16 hi = __float2bfloat16(v);
        __nv_bfloat16 lo = __float2bfloat16(v - __bfloat162float(hi));
        __nv_bfloat16* row = dst + (size_t)m * (3 * Kp);
        row[k] = hi;
        row[Kp + k] = hi;
        row[2 * Kp + k] = lo;
    }
}

__global__ void k_splitB(const float* __restrict__ W, __nv_bfloat16* __restrict__ Bt,
                         int K, int N, int Kp)
{
    __shared__ float tile[32][33];
    int kb = blockIdx.y * 32, nb = blockIdx.x * 32;
    int tx = threadIdx.x, ty = threadIdx.y;
    for (int r = ty; r < 32; r += 8) {
        int k = kb + r, n = nb + tx;
        tile[r][tx] = (k < K && n < N) ? W[(size_t)k * N + n] : 0.f;
    }
    __syncthreads();
    for (int r = ty; r < 32; r += 8) {
        int n = nb + r, k = kb + tx;
        if (n < N && k < K) {
            float v = tile[tx][r];
            __nv_bfloat16 hi = __float2bfloat16(v);
            __nv_bfloat16 lo = __float2bfloat16(v - __bfloat162float(hi));
            __nv_bfloat16* row = Bt + (size_t)n * (3 * Kp);
            row[k] = hi;
            row[Kp + k] = lo;
            row[2 * Kp + k] = hi;
        }
    }
}

// ===================== mma.sync GEMM =====================
// CTA 128x128, 4 warps (2x2), warp tile 64x64, BK=64, 3 stages, 2 CTAs/SM.
// ONE barrier per K-step. EPI=0: fp32 C. EPI=1: split-bf16 write into A2.
#define ROWB 144
#define A_STG (128 * ROWB)
#define B_STG (128 * ROWB)
#define STG   (A_STG + B_STG)
#define GEMM_SMEM (3 * STG)

__device__ __forceinline__ void ldm4(uint32_t* r, uint32_t addr) {
    asm volatile("ldmatrix.sync.aligned.m8n8.x4.shared.b16 {%0,%1,%2,%3}, [%4];"
        : "=r"(r[0]), "=r"(r[1]), "=r"(r[2]), "=r"(r[3]) : "r"(addr));
}
__device__ __forceinline__ void mma16816(float* c, const uint32_t* a,
                                         uint32_t b0, uint32_t b1) {
    asm volatile("mma.sync.aligned.m16n8k16.row.col.f32.bf16.bf16.f32 "
        "{%0,%1,%2,%3}, {%4,%5,%6,%7}, {%8,%9}, {%0,%1,%2,%3};"
        : "+f"(c[0]), "+f"(c[1]), "+f"(c[2]), "+f"(c[3])
        : "r"(a[0]), "r"(a[1]), "r"(a[2]), "r"(a[3]), "r"(b0), "r"(b1));
}

__device__ __forceinline__ uint32_t packbf2(float v0, float v1) {
    __nv_bfloat162 h = __floats2bfloat162_rn(v0, v1);
    return *(uint32_t*)&h;
}
// split-write two adjacent columns of one row into [hi | hi | lo] layout
__device__ __forceinline__ void wsplit2(__nv_bfloat16* base, int r, size_t KsT,
                                        int KsP, int col, float v0, float v1) {
    __nv_bfloat16 h0 = __float2bfloat16(v0);
    __nv_bfloat16 h1 = __float2bfloat16(v1);
    float l0f = v0 - __bfloat162float(h0);
    float l1f = v1 - __bfloat162float(h1);
    uint32_t hp; { __nv_bfloat162 hh; hh.x = h0; hh.y = h1; hp = *(uint32_t*)&hh; }
    uint32_t lp = packbf2(l0f, l1f);
    __nv_bfloat16* row = base + (size_t)r * KsT;
    *(uint32_t*)(row + col) = hp;
    *(uint32_t*)(row + KsP + col) = hp;
    *(uint32_t*)(row + 2 * KsP + col) = lp;
}

template <int EPI>
__global__ __launch_bounds__(128, 2) void k_mma(
    const __nv_bfloat16* __restrict__ A, const __nv_bfloat16* __restrict__ B,
    const float* __restrict__ bias, float* __restrict__ C,
    __nv_bfloat16* __restrict__ Csp, int KsP,
    int Kt, int steps, int Nreal)
{
    extern __shared__ char smem[];
    uint32_t sb = smem_u32(smem);
    int tid = threadIdx.x;
    int lane = tid & 31, wid = tid >> 5;
    int wm = wid & 1, wn = wid >> 1;
    int bm = blockIdx.y * 128, bn = blockIdx.x * 128;

    const char* Abase = (const char*)A + (size_t)bm * Kt * 2;
    const char* Bbase = (const char*)B + (size_t)bn * Kt * 2;
    size_t gsA = (size_t)Kt * 2;

    auto load_stage = [&](int s, int slot) {
        size_t kb = (size_t)s * 128;
        uint32_t base = sb + slot * STG;
        #pragma unroll
        for (int i = 0; i < 8; i++) {
            int c = tid + i * 128;
            int row = c >> 3, kc = c & 7;
            uint32_t dst = base + row * ROWB + kc * 16;
            const char* src = Abase + (size_t)row * gsA + kb + kc * 16;
            asm volatile("cp.async.cg.shared.global [%0], [%1], 16;"
                         :: "r"(dst), "l"(src));
        }
        #pragma unroll
        for (int i = 0; i < 8; i++) {
            int c = tid + i * 128;
            int row = c >> 3, kc = c & 7;
            uint32_t dst = base + A_STG + row * ROWB + kc * 16;
            const char* src = Bbase + (size_t)row * gsA + kb + kc * 16;
            asm volatile("cp.async.cg.shared.global [%0], [%1], 16;"
                         :: "r"(dst), "l"(src));
        }
    };

    float acc[4][8][4];
    #pragma unroll
    for (int i = 0; i < 4; i++)
        #pragma unroll
        for (int j = 0; j < 8; j++)
            #pragma unroll
            for (int q = 0; q < 4; q++) acc[i][j][q] = 0.f;

    load_stage(0, 0);
    asm volatile("cp.async.commit_group;" ::: "memory");
    load_stage(1, 1);
    asm volatile("cp.async.commit_group;" ::: "memory");

    int lr = lane & 15;
    int lc = (lane >> 4) * 16;

    for (int j = 0; j < steps; j++) {
        asm volatile("cp.async.wait_group 1;" ::: "memory");
        __syncthreads();           // single barrier per step

        if (j + 2 < steps) load_stage(j + 2, (j + 2) % 3);
        asm volatile("cp.async.commit_group;" ::: "memory");

        uint32_t sA = sb + (j % 3) * STG;
        uint32_t sB = sA + A_STG;
        uint32_t aA = sA + (wm * 64 + lr) * ROWB + lc;
        uint32_t aB = sB + (wn * 64 + lr) * ROWB + lc;

        #pragma unroll
        for (int ks = 0; ks < 4; ks++) {
            uint32_t a[4][4], b[4][4];
            #pragma unroll
            for (int mi = 0; mi < 4; mi++)
                ldm4(a[mi], aA + mi * 16 * ROWB + ks * 32);
            #pragma unroll
            for (int ng = 0; ng < 4; ng++)
                ldm4(b[ng], aB + ng * 16 * ROWB + ks * 32);
            #pragma unroll
            for (int mi = 0; mi < 4; mi++)
                #pragma unroll
                for (int ng = 0; ng < 4; ng++) {
                    mma16816(acc[mi][2 * ng],     a[mi], b[ng][0], b[ng][2]);
                    mma16816(acc[mi][2 * ng + 1], a[mi], b[ng][1], b[ng][3]);
                }
        }
        // NOTE: no second barrier — next iteration's top barrier orders
        // compute(j) before loads(j+3) into slot j%3.
    }

    int r0base = bm + wm * 64 + (lane >> 2);
    int c0base = bn + wn * 64 + (lane & 3) * 2;
    #pragma unroll
    for (int mi = 0; mi < 4; mi++) {
        #pragma unroll
        for (int ni = 0; ni < 8; ni++) {
            int col = c0base + ni * 8;
            if (EPI == 1 && col >= Nreal) continue;  // col even, Nreal even
            float bv0 = __ldg(&bias[col]);
            float bv1 = __ldg(&bias[col + 1]);
            int r0 = r0base + mi * 16;
            int r1 = r0 + 8;
            float v0 = fmaxf(acc[mi][ni][0] + bv0, 0.f);
            float v1 = fmaxf(acc[mi][ni][1] + bv1, 0.f);
            float v2 = fmaxf(acc[mi][ni][2] + bv0, 0.f);
            float v3 = fmaxf(acc[mi][ni][3] + bv1, 0.f);
            if (EPI == 0) {
                *(float2*)(C + (size_t)r0 * Nreal + col) = make_float2(v0, v1);
                *(float2*)(C + (size_t)r1 * Nreal + col) = make_float2(v2, v3);
            } else {
                wsplit2(Csp, r0, (size_t)(3 * KsP), KsP, col, v0, v1);
                wsplit2(Csp, r1, (size_t)(3 * KsP), KsP, col, v2, v3);
            }
        }
    }
}

// ===================== final skinny layer =====================
__global__ void k_lin3(const float* __restrict__ H, const float* __restrict__ W,
                       const float* __restrict__ b, float* __restrict__ out, int M)
{
    int idx = blockIdx.x * blockDim.x + threadIdx.x;
    if (idx >= M * 9) return;
    int row = idx / 9, c = idx - row * 9;
    const float* h = H + (size_t)row * 1024;
    float acc = 0.f;
    #pragma unroll 8
    for (int k = 0; k < 1024; k++) acc += h[k] * W[k * 9 + c];
    out[idx] = acc + b[c];
}

// ===================== launch =====================
extern "C" void kernel_launch(void* const* d_in, const int* in_sizes, int n_in,
                              void* d_out, int out_size)
{
    const float* x   = (const float*)d_in[0];
    const void*  ei  = d_in[1];
    const float* W1  = (const float*)d_in[3];
    const float* a1s = (const float*)d_in[4];
    const float* a1d = (const float*)d_in[5];
    const float* b1  = (const float*)d_in[6];
    const float* W2  = (const float*)d_in[7];
    const float* a2s = (const float*)d_in[8];
    const float* a2d = (const float*)d_in[9];
    const float* b2  = (const float*)d_in[10];
    const float* W3  = (const float*)d_in[11];
    const float* a3s = (const float*)d_in[12];
    const float* a3d = (const float*)d_in[13];
    const float* b3  = (const float*)d_in[14];
    const float* lW1 = (const float*)d_in[15];
    const float* lb1 = (const float*)d_in[16];
    const float* lW2 = (const float*)d_in[17];
    const float* lb2 = (const float*)d_in[18];
    const float* lW3 = (const float*)d_in[19];
    const float* lb3 = (const float*)d_in[20];

    int N   = in_sizes[0];
    int B   = N / NPG;
    int E   = in_sizes[1] / 2;
    int EPG = E / B;

    float *F, *H;
    __nv_bfloat16 *A1, *B1, *A2, *B2;
    cudaGetSymbolAddress((void**)&F, g_F);
    cudaGetSymbolAddress((void**)&H, g_H);
    cudaGetSymbolAddress((void**)&A1, g_A1);
    cudaGetSymbolAddress((void**)&B1, g_B1);
    cudaGetSymbolAddress((void**)&A2, g_A2);
    cudaGetSymbolAddress((void**)&B2, g_B2);

    cudaFuncSetAttribute(k_mma<0>,
        cudaFuncAttributeMaxDynamicSharedMemorySize, GEMM_SMEM);
    cudaFuncSetAttribute(k_mma<1>,
        cudaFuncAttributeMaxDynamicSharedMemorySize, GEMM_SMEM);

    k_sniff<<<1, 32>>>((const int*)ei);
    k_res0<<<B, 64>>>(x, F);

    k_gat<1, 8><<<B, 256>>>(x, NPG, ei, E, EPG, W1, a1s, a1d, b1,
                            F, OFF_RES1, OFF_OUT1);
    k_gat<8, 64><<<B, 256>>>(F + OFF_RES1, FDIM, ei, E, EPG, W2, a2s, a2d, b2,
                             F, OFF_RES2, OFF_OUT2);
    k_gat<64, 9><<<B, 256>>>(F + OFF_RES2, FDIM, ei, E, EPG, W3, a3s, a3d, b3,
                             F, OFF_RES3, OFF_OUT3);

    {
        dim3 blk(32, 8);
        dim3 g1((5000 + 31) / 32, (3280 + 31) / 32);
        k_splitB<<<g1, blk>>>(lW1, B1, 3280, 5000, K1P);
        dim3 g2((1024 + 31) / 32, (5000 + 31) / 32);
        k_splitB<<<g2, blk>>>(lW2, B2, 5000, 1024, K2P);
    }

    k_splitA<<<4096, 256>>>(F, A1, B, FDIM, K1P);

    // GEMM1: writes A2' (split bf16) directly — no fp32 G, no splitA2
    {
        dim3 grid(N1PAD / 128, BGR / 128);
        k_mma<1><<<grid, 128, GEMM_SMEM>>>(A1, B1, lb1, (float*)nullptr,
                                           A2, K2P, K1T, K1T / 64, 5000);
    }

    // GEMM2: fp32 H out
    {
        dim3 grid(1024 / 128, BGR / 128);
        k_mma<0><<<grid, 128, GEMM_SMEM>>>(A2, B2, lb2, H,
                                           (__nv_bfloat16*)nullptr, 0,
                                           K2T, K2T / 64, 1024);
    }

    k_lin3<<<(B * 9 + 255) / 256, 256>>>(H, lW3, lb3, (float*)d_out, B);
}

// round 8
// speedup vs baseline: 2.5998x; 1.0356x over previous
#include <cuda_runtime.h>
#include <cuda_bf16.h>
#include <stdint.h>

#define NPG  39
#define FDIM 3280
#define BGR  4096
#define MAXE (NPG * 9)

#define OFF_RES1 39
#define OFF_RES2 351
#define OFF_RES3 2847
#define OFF_OUT0 3198
#define OFF_OUT1 3199
#define OFF_OUT2 3207
#define OFF_OUT3 3271

#define K1P 3328
#define K1T (3*K1P)      // 9984
#define K2P 5056
#define K2T (3*K2P)      // 15168
#define N1PAD 5120

__device__ float g_F[(size_t)BGR * FDIM];
__device__ float g_H[(size_t)BGR * 1024];
__device__ __nv_bfloat16 g_A1[(size_t)BGR * K1T];
__device__ __nv_bfloat16 g_B1[(size_t)N1PAD * K1T];
__device__ __nv_bfloat16 g_A2[(size_t)BGR * K2T];
__device__ __nv_bfloat16 g_B2[(size_t)1024 * K2T];
__device__ int g_is64;

__device__ __forceinline__ uint32_t smem_u32(const void* p) {
    uint32_t a;
    asm("{ .reg .u64 t; cvta.to.shared.u64 t, %1; cvt.u32.u64 %0, t; }"
        : "=r"(a) : "l"(p));
    return a;
}

// ===================== misc small kernels =====================
__global__ void k_sniff(const int* __restrict__ ei) {
    if (threadIdx.x == 0) g_is64 = (ei[8] == 0) ? 1 : 0;
}

__global__ void k_res0(const float* __restrict__ x, float* __restrict__ F) {
    int g = blockIdx.x;
    __shared__ float sx[NPG];
    int t = threadIdx.x;
    if (t < NPG) {
        float v = x[g * NPG + t];
        sx[t] = v;
        F[(size_t)g * FDIM + t] = v;
    }
    __syncthreads();
    if (t == 0) {
        float mv = sx[0];
        for (int i = 1; i < NPG; i++) mv = fmaxf(mv, sx[i]);
        F[(size_t)g * FDIM + OFF_OUT0] = mv;
    }
}

__device__ __forceinline__ unsigned fenc(float f) {
    unsigned u = __float_as_uint(f);
    return (u & 0x80000000u) ? ~u : (u | 0x80000000u);
}
__device__ __forceinline__ float fdec(unsigned u) {
    return (u & 0x80000000u) ? __uint_as_float(u & 0x7FFFFFFFu)
                             : __uint_as_float(~u);
}

// ===================== GAT layer (counting-sort + float4) =====================
template <int FIN, int FOUT>
__global__ __launch_bounds__(256) void k_gat(
    const float* __restrict__ X, int gstride,
    const void* __restrict__ edges, int E, int EPG,
    const float* __restrict__ W, const float* __restrict__ as_,
    const float* __restrict__ ad_, const float* __restrict__ bias,
    float* __restrict__ F, int res_off, int max_off)
{
    __shared__ __align__(16) float sx[NPG * FIN];
    __shared__ __align__(16) float sW[FIN * FOUT];
    __shared__ float sas[FOUT], sad[FOUT], sb[FOUT];
    __shared__ __align__(16) float sh[NPG * FOUT];
    __shared__ __align__(16) float sout[NPG * FOUT];
    __shared__ float ss[NPG], sd[NPG], sden[NPG];
    __shared__ unsigned sm[NPG];
    __shared__ float ew[MAXE];
    __shared__ short els[MAXE], eld[MAXE];
    __shared__ short sse[MAXE];
    __shared__ float sew[MAXE];
    __shared__ int cnt[NPG + 1], off[NPG];

    constexpr bool V4 = (FOUT % 4 == 0);

    int g = blockIdx.x;
    int t = threadIdx.x;
    const float* xg = X + (size_t)g * gstride;
    int nE = EPG + NPG;

    for (int i = t; i < NPG * FIN; i += 256) sx[i] = xg[i];
    for (int i = t; i < FIN * FOUT; i += 256) sW[i] = W[i];
    if (t < FOUT) { sas[t] = as_[t]; sad[t] = ad_[t]; sb[t] = bias[t]; }
    if (t < NPG + 1) cnt[t] = 0;
    __syncthreads();

    // h = x @ W
    if (V4) {
        constexpr int F4 = FOUT / 4;
        for (int idx = t; idx < NPG * F4; idx += 256) {
            int i = idx / F4, f4 = idx - i * F4;
            float4 a = make_float4(0.f, 0.f, 0.f, 0.f);
            #pragma unroll
            for (int k = 0; k < FIN; k++) {
                float xv = sx[i * FIN + k];
                float4 wv = *(const float4*)&sW[k * FOUT + f4 * 4];
                a.x += xv * wv.x; a.y += xv * wv.y;
                a.z += xv * wv.z; a.w += xv * wv.w;
            }
            *(float4*)&sh[i * FOUT + f4 * 4] = a;
        }
    } else {
        for (int idx = t; idx < NPG * FOUT; idx += 256) {
            int i = idx / FOUT, f = idx - i * FOUT;
            float a = 0.f;
            #pragma unroll
            for (int k = 0; k < FIN; k++) a += sx[i * FIN + k] * sW[k * FOUT + f];
            sh[idx] = a;
        }
    }
    __syncthreads();

    for (int i = t; i < NPG; i += 256) {
        float a = 0.f, b = 0.f;
        #pragma unroll
        for (int f = 0; f < FOUT; f++) {
            a += sh[i * FOUT + f] * sas[f];
            b += sh[i * FOUT + f] * sad[f];
        }
        ss[i] = a; sd[i] = b; sm[i] = 0u;
    }
    __syncthreads();

    bool is64 = (g_is64 != 0);
    long long node0 = (long long)g * NPG;

    for (int e = t; e < nE; e += 256) {
        int ls, ld;
        if (e < EPG) {
            long long ge = (long long)g * EPG + e;
            long long sv, dv;
            if (is64) {
                const long long* p = (const long long*)edges;
                sv = p[ge]; dv = p[ge + E];
            } else {
                const int* p = (const int*)edges;
                sv = p[ge]; dv = p[ge + E];
            }
            ls = (int)(sv - node0);
            ld = (int)(dv - node0);
        } else {
            ls = ld = e - EPG;
        }
        els[e] = (short)ls; eld[e] = (short)ld;
        float ev = ss[ls] + sd[ld];
        ev = ev > 0.f ? ev : 0.2f * ev;
        ew[e] = ev;
        atomicMax(&sm[ld], fenc(ev));
        atomicAdd(&cnt[ld], 1);
    }
    __syncthreads();

    if (t == 0) {
        int s = 0;
        for (int i = 0; i < NPG; i++) {
            int c = cnt[i];
            cnt[i] = s; off[i] = s;
            s += c;
        }
        cnt[NPG] = s;
    }
    __syncthreads();

    for (int e = t; e < nE; e += 256) {
        int ld = eld[e];
        int pos = atomicAdd(&off[ld], 1);
        sew[pos] = __expf(ew[e] - fdec(sm[ld]));
        sse[pos] = els[e];
    }
    __syncthreads();

    for (int i = t; i < NPG; i += 256) {
        float s = 0.f;
        for (int e = cnt[i]; e < cnt[i + 1]; e++) s += sew[e];
        sden[i] = s;
    }
    __syncthreads();

    // aggregation: per (node, feature-group) gather
    float* Fg = F + (size_t)g * FDIM;
    if (V4) {
        constexpr int F4 = FOUT / 4;
        for (int idx = t; idx < NPG * F4; idx += 256) {
            int i = idx / F4, f4 = idx - i * F4;
            float4 a = make_float4(0.f, 0.f, 0.f, 0.f);
            int e0 = cnt[i], e1 = cnt[i + 1];
            for (int e = e0; e < e1; e++) {
                float w = sew[e];
                float4 hv = *(const float4*)&sh[(int)sse[e] * FOUT + f4 * 4];
                a.x += w * hv.x; a.y += w * hv.y;
                a.z += w * hv.z; a.w += w * hv.w;
            }
            float inv = 1.f / (sden[i] + 1e-16f);
            int base = i * FOUT + f4 * 4;
            float v0 = fmaxf(a.x * inv + sb[f4 * 4 + 0], 0.f);
            float v1 = fmaxf(a.y * inv + sb[f4 * 4 + 1], 0.f);
            float v2 = fmaxf(a.z * inv + sb[f4 * 4 + 2], 0.f);
            float v3 = fmaxf(a.w * inv + sb[f4 * 4 + 3], 0.f);
            *(float4*)&sout[base] = make_float4(v0, v1, v2, v3);
            Fg[res_off + base + 0] = v0;
            Fg[res_off + base + 1] = v1;
            Fg[res_off + base + 2] = v2;
            Fg[res_off + base + 3] = v3;
        }
    } else {
        for (int idx = t; idx < NPG * FOUT; idx += 256) {
            int i = idx / FOUT, f = idx - i * FOUT;
            float a = 0.f;
            int e0 = cnt[i], e1 = cnt[i + 1];
            for (int e = e0; e < e1; e++)
                a += sew[e] * sh[(int)sse[e] * FOUT + f];
            float v = a / (sden[i] + 1e-16f) + sb[f];
            v = fmaxf(v, 0.f);
            Fg[res_off + idx] = v;
            sout[idx] = v;
        }
    }
    __syncthreads();
    for (int f = t; f < FOUT; f += 256) {
        float mv = sout[f];
        for (int i = 1; i < NPG; i++) mv = fmaxf(mv, sout[i * FOUT + f]);
        Fg[max_off + f] = mv;
    }
}

// ===================== split/prep kernels =====================
// One row per block, float4 reads, 8B packed bf16 writes. K % 4 == 0.
__global__ __launch_bounds__(256) void k_splitA(
    const float* __restrict__ src, __nv_bfloat16* __restrict__ dst,
    int K, int Kp)
{
    int m = blockIdx.x;
    const float4* srow = (const float4*)(src + (size_t)m * K);
    __nv_bfloat16* drow = dst + (size_t)m * (3 * Kp);
    int K4 = K >> 2;
    for (int k4 = threadIdx.x; k4 < K4; k4 += 256) {
        float4 v = srow[k4];
        __nv_bfloat162 h01 = __floats2bfloat162_rn(v.x, v.y);
        __nv_bfloat162 h23 = __floats2bfloat162_rn(v.z, v.w);
        __nv_bfloat162 l01 = __floats2bfloat162_rn(
            v.x - __bfloat162float(h01.x), v.y - __bfloat162float(h01.y));
        __nv_bfloat162 l23 = __floats2bfloat162_rn(
            v.z - __bfloat162float(h23.x), v.w - __bfloat162float(h23.y));
        uint2 hp = make_uint2(*(uint32_t*)&h01, *(uint32_t*)&h23);
        uint2 lp = make_uint2(*(uint32_t*)&l01, *(uint32_t*)&l23);
        *(uint2*)(drow + k4 * 4) = hp;
        *(uint2*)(drow + Kp + k4 * 4) = hp;
        *(uint2*)(drow + 2 * Kp + k4 * 4) = lp;
    }
}

__global__ void k_splitB(const float* __restrict__ W, __nv_bfloat16* __restrict__ Bt,
                         int K, int N, int Kp)
{
    __shared__ float tile[32][33];
    int kb = blockIdx.y * 32, nb = blockIdx.x * 32;
    int tx = threadIdx.x, ty = threadIdx.y;
    for (int r = ty; r < 32; r += 8) {
        int k = kb + r, n = nb + tx;
        tile[r][tx] = (k < K && n < N) ? W[(size_t)k * N + n] : 0.f;
    }
    __syncthreads();
    for (int r = ty; r < 32; r += 8) {
        int n = nb + r, k = kb + tx;
        if (n < N && k < K) {
            float v = tile[tx][r];
            __nv_bfloat16 hi = __float2bfloat16(v);
            __nv_bfloat16 lo = __float2bfloat16(v - __bfloat162float(hi));
            __nv_bfloat16* row = Bt + (size_t)n * (3 * Kp);
            row[k] = hi;
            row[Kp + k] = lo;
            row[2 * Kp + k] = hi;
        }
    }
}

// ===================== mma.sync GEMM (unchanged from R6) =====================
#define ROWB 144
#define A_STG (128 * ROWB)
#define B_STG (128 * ROWB)
#define STG   (A_STG + B_STG)
#define GEMM_SMEM (3 * STG)

__device__ __forceinline__ void ldm4(uint32_t* r, uint32_t addr) {
    asm volatile("ldmatrix.sync.aligned.m8n8.x4.shared.b16 {%0,%1,%2,%3}, [%4];"
        : "=r"(r[0]), "=r"(r[1]), "=r"(r[2]), "=r"(r[3]) : "r"(addr));
}
__device__ __forceinline__ void mma16816(float* c, const uint32_t* a,
                                         uint32_t b0, uint32_t b1) {
    asm volatile("mma.sync.aligned.m16n8k16.row.col.f32.bf16.bf16.f32 "
        "{%0,%1,%2,%3}, {%4,%5,%6,%7}, {%8,%9}, {%0,%1,%2,%3};"
        : "+f"(c[0]), "+f"(c[1]), "+f"(c[2]), "+f"(c[3])
        : "r"(a[0]), "r"(a[1]), "r"(a[2]), "r"(a[3]), "r"(b0), "r"(b1));
}

__device__ __forceinline__ uint32_t packbf2(float v0, float v1) {
    __nv_bfloat162 h = __floats2bfloat162_rn(v0, v1);
    return *(uint32_t*)&h;
}
__device__ __forceinline__ void wsplit2(__nv_bfloat16* base, int r, size_t KsT,
                                        int KsP, int col, float v0, float v1) {
    __nv_bfloat16 h0 = __float2bfloat16(v0);
    __nv_bfloat16 h1 = __float2bfloat16(v1);
    float l0f = v0 - __bfloat162float(h0);
    float l1f = v1 - __bfloat162float(h1);
    uint32_t hp; { __nv_bfloat162 hh; hh.x = h0; hh.y = h1; hp = *(uint32_t*)&hh; }
    uint32_t lp = packbf2(l0f, l1f);
    __nv_bfloat16* row = base + (size_t)r * KsT;
    *(uint32_t*)(row + col) = hp;
    *(uint32_t*)(row + KsP + col) = hp;
    *(uint32_t*)(row + 2 * KsP + col) = lp;
}

template <int EPI>
__global__ __launch_bounds__(128, 2) void k_mma(
    const __nv_bfloat16* __restrict__ A, const __nv_bfloat16* __restrict__ B,
    const float* __restrict__ bias, float* __restrict__ C,
    __nv_bfloat16* __restrict__ Csp, int KsP,
    int Kt, int steps, int Nreal)
{
    extern __shared__ char smem[];
    uint32_t sb = smem_u32(smem);
    int tid = threadIdx.x;
    int lane = tid & 31, wid = tid >> 5;
    int wm = wid & 1, wn = wid >> 1;
    int bm = blockIdx.y * 128, bn = blockIdx.x * 128;

    const char* Abase = (const char*)A + (size_t)bm * Kt * 2;
    const char* Bbase = (const char*)B + (size_t)bn * Kt * 2;
    size_t gsA = (size_t)Kt * 2;

    auto load_stage = [&](int s, int slot) {
        size_t kb = (size_t)s * 128;
        uint32_t base = sb + slot * STG;
        #pragma unroll
        for (int i = 0; i < 8; i++) {
            int c = tid + i * 128;
            int row = c >> 3, kc = c & 7;
            uint32_t dst = base + row * ROWB + kc * 16;
            const char* src = Abase + (size_t)row * gsA + kb + kc * 16;
            asm volatile("cp.async.cg.shared.global [%0], [%1], 16;"
                         :: "r"(dst), "l"(src));
        }
        #pragma unroll
        for (int i = 0; i < 8; i++) {
            int c = tid + i * 128;
            int row = c >> 3, kc = c & 7;
            uint32_t dst = base + A_STG + row * ROWB + kc * 16;
            const char* src = Bbase + (size_t)row * gsA + kb + kc * 16;
            asm volatile("cp.async.cg.shared.global [%0], [%1], 16;"
                         :: "r"(dst), "l"(src));
        }
    };

    float acc[4][8][4];
    #pragma unroll
    for (int i = 0; i < 4; i++)
        #pragma unroll
        for (int j = 0; j < 8; j++)
            #pragma unroll
            for (int q = 0; q < 4; q++) acc[i][j][q] = 0.f;

    load_stage(0, 0);
    asm volatile("cp.async.commit_group;" ::: "memory");
    load_stage(1, 1);
    asm volatile("cp.async.commit_group;" ::: "memory");

    int lr = lane & 15;
    int lc = (lane >> 4) * 16;

    for (int j = 0; j < steps; j++) {
        asm volatile("cp.async.wait_group 1;" ::: "memory");
        __syncthreads();

        if (j + 2 < steps) load_stage(j + 2, (j + 2) % 3);
        asm volatile("cp.async.commit_group;" ::: "memory");

        uint32_t sA = sb + (j % 3) * STG;
        uint32_t sB = sA + A_STG;
        uint32_t aA = sA + (wm * 64 + lr) * ROWB + lc;
        uint32_t aB = sB + (wn * 64 + lr) * ROWB + lc;

        #pragma unroll
        for (int ks = 0; ks < 4; ks++) {
            uint32_t a[4][4], b[4][4];
            #pragma unroll
            for (int mi = 0; mi < 4; mi++)
                ldm4(a[mi], aA + mi * 16 * ROWB + ks * 32);
            #pragma unroll
            for (int ng = 0; ng < 4; ng++)
                ldm4(b[ng], aB + ng * 16 * ROWB + ks * 32);
            #pragma unroll
            for (int mi = 0; mi < 4; mi++)
                #pragma unroll
                for (int ng = 0; ng < 4; ng++) {
                    mma16816(acc[mi][2 * ng],     a[mi], b[ng][0], b[ng][2]);
                    mma16816(acc[mi][2 * ng + 1], a[mi], b[ng][1], b[ng][3]);
                }
        }
    }

    int r0base = bm + wm * 64 + (lane >> 2);
    int c0base = bn + wn * 64 + (lane & 3) * 2;
    #pragma unroll
    for (int mi = 0; mi < 4; mi++) {
        #pragma unroll
        for (int ni = 0; ni < 8; ni++) {
            int col = c0base + ni * 8;
            if (EPI == 1 && col >= Nreal) continue;
            float bv0 = __ldg(&bias[col]);
            float bv1 = __ldg(&bias[col + 1]);
            int r0 = r0base + mi * 16;
            int r1 = r0 + 8;
            float v0 = fmaxf(acc[mi][ni][0] + bv0, 0.f);
            float v1 = fmaxf(acc[mi][ni][1] + bv1, 0.f);
            float v2 = fmaxf(acc[mi][ni][2] + bv0, 0.f);
            float v3 = fmaxf(acc[mi][ni][3] + bv1, 0.f);
            if (EPI == 0) {
                *(float2*)(C + (size_t)r0 * Nreal + col) = make_float2(v0, v1);
                *(float2*)(C + (size_t)r1 * Nreal + col) = make_float2(v2, v3);
            } else {
                wsplit2(Csp, r0, (size_t)(3 * KsP), KsP, col, v0, v1);
                wsplit2(Csp, r1, (size_t)(3 * KsP), KsP, col, v2, v3);
            }
        }
    }
}

// ===================== final skinny layer: warp per row =====================
__global__ __launch_bounds__(256) void k_lin3(
    const float* __restrict__ H, const float* __restrict__ W,
    const float* __restrict__ b, float* __restrict__ out)
{
    __shared__ float Wt[9][1024];
    __shared__ float sb9[9];
    int t = threadIdx.x;
    for (int i = t; i < 9 * 1024; i += 256) {
        int c = i / 1024, k = i - c * 1024;
        Wt[c][k] = W[k * 9 + c];
    }
    if (t < 9) sb9[t] = b[t];
    __syncthreads();

    int w = t >> 5, l = t & 31;
    int row = blockIdx.x * 8 + w;
    const float* h = H + (size_t)row * 1024;

    float acc[9];
    #pragma unroll
    for (int c = 0; c < 9; c++) acc[c] = 0.f;
    #pragma unroll 4
    for (int i = 0; i < 32; i++) {
        int k = l + 32 * i;
        float hv = h[k];
        #pragma unroll
        for (int c = 0; c < 9; c++) acc[c] += hv * Wt[c][k];
    }
    #pragma unroll
    for (int o = 16; o; o >>= 1)
        #pragma unroll
        for (int c = 0; c < 9; c++)
            acc[c] += __shfl_xor_sync(0xFFFFFFFFu, acc[c], o);
    if (l == 0) {
        #pragma unroll
        for (int c = 0; c < 9; c++) out[row * 9 + c] = acc[c] + sb9[c];
    }
}

// ===================== launch =====================
extern "C" void kernel_launch(void* const* d_in, const int* in_sizes, int n_in,
                              void* d_out, int out_size)
{
    const float* x   = (const float*)d_in[0];
    const void*  ei  = d_in[1];
    const float* W1  = (const float*)d_in[3];
    const float* a1s = (const float*)d_in[4];
    const float* a1d = (const float*)d_in[5];
    const float* b1  = (const float*)d_in[6];
    const float* W2  = (const float*)d_in[7];
    const float* a2s = (const float*)d_in[8];
    const float* a2d = (const float*)d_in[9];
    const float* b2  = (const float*)d_in[10];
    const float* W3  = (const float*)d_in[11];
    const float* a3s = (const float*)d_in[12];
    const float* a3d = (const float*)d_in[13];
    const float* b3  = (const float*)d_in[14];
    const float* lW1 = (const float*)d_in[15];
    const float* lb1 = (const float*)d_in[16];
    const float* lW2 = (const float*)d_in[17];
    const float* lb2 = (const float*)d_in[18];
    const float* lW3 = (const float*)d_in[19];
    const float* lb3 = (const float*)d_in[20];

    int N   = in_sizes[0];
    int B   = N / NPG;
    int E   = in_sizes[1] / 2;
    int EPG = E / B;

    float *F, *H;
    __nv_bfloat16 *A1, *B1, *A2, *B2;
    cudaGetSymbolAddress((void**)&F, g_F);
    cudaGetSymbolAddress((void**)&H, g_H);
    cudaGetSymbolAddress((void**)&A1, g_A1);
    cudaGetSymbolAddress((void**)&B1, g_B1);
    cudaGetSymbolAddress((void**)&A2, g_A2);
    cudaGetSymbolAddress((void**)&B2, g_B2);

    cudaFuncSetAttribute(k_mma<0>,
        cudaFuncAttributeMaxDynamicSharedMemorySize, GEMM_SMEM);
    cudaFuncSetAttribute(k_mma<1>,
        cudaFuncAttributeMaxDynamicSharedMemorySize, GEMM_SMEM);

    k_sniff<<<1, 32>>>((const int*)ei);
    k_res0<<<B, 64>>>(x, F);

    k_gat<1, 8><<<B, 256>>>(x, NPG, ei, E, EPG, W1, a1s, a1d, b1,
                            F, OFF_RES1, OFF_OUT1);
    k_gat<8, 64><<<B, 256>>>(F + OFF_RES1, FDIM, ei, E, EPG, W2, a2s, a2d, b2,
                             F, OFF_RES2, OFF_OUT2);
    k_gat<64, 9><<<B, 256>>>(F + OFF_RES2, FDIM, ei, E, EPG, W3, a3s, a3d, b3,
                             F, OFF_RES3, OFF_OUT3);

    {
        dim3 blk(32, 8);
        dim3 g1((5000 + 31) / 32, (3280 + 31) / 32);
        k_splitB<<<g1, blk>>>(lW1, B1, 3280, 5000, K1P);
        dim3 g2((1024 + 31) / 32, (5000 + 31) / 32);
        k_splitB<<<g2, blk>>>(lW2, B2, 5000, 1024, K2P);
    }

    k_splitA<<<BGR, 256>>>(F, A1, FDIM, K1P);

    // GEMM1: writes A2' (split bf16) directly
    {
        dim3 grid(N1PAD / 128, BGR / 128);
        k_mma<1><<<grid, 128, GEMM_SMEM>>>(A1, B1, lb1, (float*)nullptr,
                                           A2, K2P, K1T, K1T / 64, 5000);
    }

    // GEMM2: fp32 H out
    {
        dim3 grid(1024 / 128, BGR / 128);
        k_mma<0><<<grid, 128, GEMM_SMEM>>>(A2, B2, lb2, H,
                                           (__nv_bfloat16*)nullptr, 0,
                                           K2T, K2T / 64, 1024);
    }

    k_lin3<<<BGR / 8, 256>>>(H, lW3, lb3, (float*)d_out);
}